// round 2
// baseline (speedup 1.0000x reference)
#include <cuda_runtime.h>
#include <cuda_bf16.h>

#define PRE     1024
#define POST    1024
#define THREADS 256
#define ELEMS   (PRE / THREADS)   // 4

// Scratch for transposed weights/delays: [POST, PRE] row-major.
// __device__ globals (allocation-free kernel_launch).
__device__ float g_wT[POST * PRE];
__device__ float g_dT[POST * PRE];

__device__ __forceinline__ float f_inf() { return __int_as_float(0x7f800000); }

// ---------------------------------------------------------------------------
// Tiled transpose of weights and delays (z = 0 -> weights, z = 1 -> delays).
// src: [PRE, POST] row-major. dst: [POST, PRE] row-major.
// ---------------------------------------------------------------------------
__global__ void transpose2_kernel(const float* __restrict__ w,
                                  const float* __restrict__ d) {
    __shared__ float tile[32][33];
    const float* src = (blockIdx.z == 0) ? w : d;
    float* dst       = (blockIdx.z == 0) ? g_wT : g_dT;

    int col = blockIdx.x * 32 + threadIdx.x;   // column in src (POST dim)
    int row = blockIdx.y * 32 + threadIdx.y;   // row in src (PRE dim)

    #pragma unroll
    for (int i = 0; i < 32; i += 8)
        tile[threadIdx.y + i][threadIdx.x] = src[(row + i) * POST + col];
    __syncthreads();

    int dcol = blockIdx.y * 32 + threadIdx.x;  // column in dst (PRE dim)
    int drow = blockIdx.x * 32 + threadIdx.y;  // row in dst (POST dim)
    #pragma unroll
    for (int i = 0; i < 32; i += 8)
        dst[(drow + i) * PRE + dcol] = tile[threadIdx.x][threadIdx.y + i];
}

// ---------------------------------------------------------------------------
// One CTA per (batch, post) pair.
// Register-resident hybrid bitonic sort:
//   cyclic layout i = tid + p*256. Partner i^j is lane tid^j of the SAME warp
//   for j < 32  -> 40 of 55 passes are pure shuffle compare-exchanges.
//   j >= 32 (15 passes) go through SMEM with a store/bar/read round trip.
// Then: two-level inclusive scan of (w, w*t), candidate spike-time solve with
// causal-window mask, block min-reduce.
// ---------------------------------------------------------------------------
__global__ __launch_bounds__(THREADS)
void equaltime_kernel(const float* __restrict__ spikes,
                      const float* __restrict__ thresholds,
                      float* __restrict__ out,
                      int B) {
    __shared__ float st[PRE];
    __shared__ float sw[PRE];
    __shared__ float s_warp_w[8];
    __shared__ float s_warp_wt[8];
    __shared__ float s_red[8];

    const int tid  = threadIdx.x;
    const int lane = tid & 31;
    const int wid  = tid >> 5;

    // b fastest: 32 consecutive blocks share the same post -> wT/dT rows are
    // L2-resident/broadcast across the concurrent wave.
    const int b    = blockIdx.x % B;
    const int post = blockIdx.x / B;

    const float* sp = spikes + b * PRE;
    const float* dT = g_dT + post * PRE;
    const float* wT = g_wT + post * PRE;

    // ---- load into registers (cyclic layout), fully coalesced ----
    float rt[ELEMS], rw[ELEMS];
    #pragma unroll
    for (int p = 0; p < ELEMS; ++p) {
        int i = tid + p * THREADS;
        rt[p] = sp[i] + dT[i];
        rw[p] = wT[i];
    }

    // ---- hybrid bitonic sort ascending by rt, carrying rw ----
    for (int k = 2; k <= PRE; k <<= 1) {
        for (int j = k >> 1; j > 0; j >>= 1) {
            if (j >= 32) {
                // cross-warp pass via SMEM snapshot
                __syncthreads();   // protect SMEM from the previous pass's readers
                #pragma unroll
                for (int p = 0; p < ELEMS; ++p) {
                    int i = tid + p * THREADS;
                    st[i] = rt[p];
                    sw[i] = rw[p];
                }
                __syncthreads();
                #pragma unroll
                for (int p = 0; p < ELEMS; ++p) {
                    int   i   = tid + p * THREADS;
                    int   ixj = i ^ j;
                    float tj  = st[ixj];
                    float wj  = sw[ixj];
                    bool asc     = ((i & k) == 0);
                    bool lower   = ((i & j) == 0);
                    bool keepmin = (lower == asc);
                    bool take    = keepmin ? (tj < rt[p]) : (tj > rt[p]);
                    if (take) { rt[p] = tj; rw[p] = wj; }
                }
            } else {
                // intra-warp pass via shuffles (no barriers, no SMEM)
                #pragma unroll
                for (int p = 0; p < ELEMS; ++p) {
                    int   i  = tid + p * THREADS;
                    float tj = __shfl_xor_sync(0xffffffffu, rt[p], j);
                    float wj = __shfl_xor_sync(0xffffffffu, rw[p], j);
                    bool asc     = ((i & k) == 0);
                    bool lower   = ((tid & j) == 0);
                    bool keepmin = (lower == asc);
                    bool take    = keepmin ? (tj < rt[p]) : (tj > rt[p]);
                    if (take) { rt[p] = tj; rw[p] = wj; }
                }
            }
        }
    }

    // ---- publish sorted arrays to SMEM (blocked access next) ----
    __syncthreads();   // last SMEM pass's stragglers may still be reading
    #pragma unroll
    for (int p = 0; p < ELEMS; ++p) {
        int i = tid + p * THREADS;
        st[i] = rt[p];
        sw[i] = rw[p];
    }
    __syncthreads();

    // ---- two-level inclusive scan of (w, w*t) in sorted order ----
    // Each thread owns ELEMS consecutive sorted elements (vectorized reload).
    float4 t4 = reinterpret_cast<const float4*>(st)[tid];
    float4 w4 = reinterpret_cast<const float4*>(sw)[tid];
    float lt[ELEMS]  = {t4.x, t4.y, t4.z, t4.w};
    float lw[ELEMS]  = {w4.x, w4.y, w4.z, w4.w};
    float lcw[ELEMS], lcwt[ELEMS];
    float cw = 0.0f, cwt = 0.0f;
    #pragma unroll
    for (int p = 0; p < ELEMS; ++p) {
        cw  += lw[p];
        cwt += lw[p] * lt[p];
        lcw[p]  = cw;     // local inclusive
        lcwt[p] = cwt;
    }

    // warp inclusive scan of per-thread totals
    float scw = cw, scwt = cwt;
    #pragma unroll
    for (int off = 1; off < 32; off <<= 1) {
        float a  = __shfl_up_sync(0xffffffffu, scw,  off);
        float a2 = __shfl_up_sync(0xffffffffu, scwt, off);
        if (lane >= off) { scw += a; scwt += a2; }
    }
    if (lane == 31) { s_warp_w[wid] = scw; s_warp_wt[wid] = scwt; }
    __syncthreads();

    // scan the 8 warp totals (lanes 0..7 of warp 0)
    if (wid == 0 && lane < 8) {
        float a  = s_warp_w[lane];
        float a2 = s_warp_wt[lane];
        #pragma unroll
        for (int off = 1; off < 8; off <<= 1) {
            float u  = __shfl_up_sync(0x000000ffu, a,  off);
            float u2 = __shfl_up_sync(0x000000ffu, a2, off);
            if (lane >= off) { a += u; a2 += u2; }
        }
        s_warp_w[lane]  = a;
        s_warp_wt[lane] = a2;
    }
    __syncthreads();

    const float basew  = (wid > 0 ? s_warp_w[wid - 1]  : 0.0f) + (scw  - cw);
    const float basewt = (wid > 0 ? s_warp_wt[wid - 1] : 0.0f) + (scwt - cwt);

    // ---- candidate solve + causal-window mask + local min ----
    const float theta = thresholds[post];
    const float INF   = f_inf();
    float vmin = INF;
    #pragma unroll
    for (int p = 0; p < ELEMS; ++p) {
        int   kk    = tid * ELEMS + p;
        float cumw  = basew  + lcw[p];
        float cumwt = basewt + lcwt[p];
        float tmp   = (cumw > 0.0f) ? (theta + cumwt) / cumw : INF;
        float sk    = lt[p];
        bool  bad   = (tmp < sk);
        if (kk < PRE - 1) {
            float sk1 = (p < ELEMS - 1) ? lt[p + 1] : st[kk + 1];
            bad = bad || (tmp > sk1);
        }
        if (!bad) vmin = fminf(vmin, tmp);
    }

    // ---- block min-reduce ----
    #pragma unroll
    for (int off = 16; off > 0; off >>= 1)
        vmin = fminf(vmin, __shfl_down_sync(0xffffffffu, vmin, off));
    if (lane == 0) s_red[wid] = vmin;
    __syncthreads();
    if (tid == 0) {
        float m = s_red[0];
        #pragma unroll
        for (int i = 1; i < 8; ++i) m = fminf(m, s_red[i]);
        out[b * POST + post] = m;
    }
}

// ---------------------------------------------------------------------------
extern "C" void kernel_launch(void* const* d_in, const int* in_sizes, int n_in,
                              void* d_out, int out_size) {
    const float* spikes     = (const float*)d_in[0];  // [B, PRE]
    const float* weights    = (const float*)d_in[1];  // [PRE, POST]
    const float* delays     = (const float*)d_in[2];  // [PRE, POST]
    const float* thresholds = (const float*)d_in[3];  // [POST]

    const int B = in_sizes[0] / PRE;

    dim3 t_tb(32, 8);
    dim3 t_tg(POST / 32, PRE / 32, 2);
    transpose2_kernel<<<t_tg, t_tb>>>(weights, delays);

    equaltime_kernel<<<B * POST, THREADS>>>(spikes, thresholds,
                                            (float*)d_out, B);
}

// round 7
// speedup vs baseline: 6.4240x; 6.4240x over previous
#include <cuda_runtime.h>
#include <cuda_bf16.h>

#define PRE     1024
#define POST    1024
#define THREADS 128
#define ELEMS   8            // PRE / THREADS

// Scratch for transposed weights/delays: [POST, PRE] row-major.
__device__ float g_wT[POST * PRE];
__device__ float g_dT[POST * PRE];

__device__ __forceinline__ float f_inf() { return __int_as_float(0x7f800000); }

// ---------------------------------------------------------------------------
// Tiled transpose of weights and delays (z = 0 -> weights, z = 1 -> delays).
// ---------------------------------------------------------------------------
__global__ void transpose2_kernel(const float* __restrict__ w,
                                  const float* __restrict__ d) {
    __shared__ float tile[32][33];
    const float* src = (blockIdx.z == 0) ? w : d;
    float* dst       = (blockIdx.z == 0) ? g_wT : g_dT;

    int col = blockIdx.x * 32 + threadIdx.x;
    int row = blockIdx.y * 32 + threadIdx.y;
    #pragma unroll
    for (int i = 0; i < 32; i += 8)
        tile[threadIdx.y + i][threadIdx.x] = src[(row + i) * POST + col];
    __syncthreads();
    int dcol = blockIdx.y * 32 + threadIdx.x;
    int drow = blockIdx.x * 32 + threadIdx.y;
    #pragma unroll
    for (int i = 0; i < 32; i += 8)
        dst[(drow + i) * PRE + dcol] = tile[threadIdx.x][threadIdx.y + i];
}

// ---------------------------------------------------------------------------
// One CTA per (batch, post). Blocked layout: thread tid owns sorted positions
// i = tid*8 + e. Sort keys are packed 32-bit: (t_bits & ~0x3FF) | element_idx.
//   j < 8        -> in-register compare-exchange (27 passes)
//   8 <= j <=128 -> warp shuffle (25 passes)
//   j >= 256     -> SMEM round trip (3 passes)
// After the sort, indices recover full-precision (t, w) from SMEM.
// ---------------------------------------------------------------------------
__global__ __launch_bounds__(THREADS)
void equaltime_kernel(const float* __restrict__ spikes,
                      const float* __restrict__ thresholds,
                      float* __restrict__ out,
                      int B) {
    __shared__ float    st_orig[PRE];   // original event times
    __shared__ float    sw_orig[PRE];   // original weights
    __shared__ unsigned skey[PRE];      // cross-warp exchange + boundary
    __shared__ float    s_ww[4], s_wwt[4], s_red[4];

    const int tid  = threadIdx.x;
    const int lane = tid & 31;
    const int wid  = tid >> 5;

    const int b    = blockIdx.x % B;     // b fastest: 32 blocks share post rows
    const int post = blockIdx.x / B;

    const float* sp = spikes + b * PRE;
    const float* dT = g_dT + post * PRE;
    const float* wT = g_wT + post * PRE;

    // ---- vectorized load, build packed keys, stash originals ----
    unsigned key[ELEMS];
    #pragma unroll
    for (int v = 0; v < 2; ++v) {
        float4 s4 = reinterpret_cast<const float4*>(sp)[tid * 2 + v];
        float4 d4 = reinterpret_cast<const float4*>(dT)[tid * 2 + v];
        float4 w4 = reinterpret_cast<const float4*>(wT)[tid * 2 + v];
        float4 t4 = make_float4(s4.x + d4.x, s4.y + d4.y,
                                s4.z + d4.z, s4.w + d4.w);
        reinterpret_cast<float4*>(st_orig)[tid * 2 + v] = t4;
        reinterpret_cast<float4*>(sw_orig)[tid * 2 + v] = w4;
        const float tt[4] = {t4.x, t4.y, t4.z, t4.w};
        #pragma unroll
        for (int q = 0; q < 4; ++q) {
            int e = v * 4 + q;
            int i = tid * ELEMS + e;
            key[e] = (__float_as_uint(tt[q]) & 0xFFFFFC00u) | (unsigned)i;
        }
    }

    // ---- bitonic sort on packed keys ----
    #pragma unroll
    for (int k = 2; k <= PRE; k <<= 1) {
        #pragma unroll
        for (int j = k >> 1; j > 0; j >>= 1) {
            if (j < ELEMS) {
                // in-register pass
                #pragma unroll
                for (int e = 0; e < ELEMS; ++e) {
                    if ((e & j) == 0) {
                        int e2 = e | j;
                        bool asc = (((tid * ELEMS + e) & k) == 0);
                        unsigned lo = min(key[e], key[e2]);
                        unsigned hi = max(key[e], key[e2]);
                        key[e]  = asc ? lo : hi;
                        key[e2] = asc ? hi : lo;
                    }
                }
            } else if (j < 256) {
                // intra-warp shuffle pass
                const int jw = j >> 3;   // lane xor distance (1..16)
                #pragma unroll
                for (int e = 0; e < ELEMS; ++e) {
                    unsigned oth = __shfl_xor_sync(0xffffffffu, key[e], jw);
                    bool asc     = (((tid * ELEMS + e) & k) == 0);
                    bool lower   = ((tid & jw) == 0);
                    bool keepmin = (lower == asc);
                    unsigned lo = min(key[e], oth);
                    unsigned hi = max(key[e], oth);
                    key[e] = keepmin ? lo : hi;
                }
            } else {
                // cross-warp pass via SMEM (j = 256, 512)
                __syncthreads();
                reinterpret_cast<uint4*>(skey)[tid * 2] =
                    make_uint4(key[0], key[1], key[2], key[3]);
                reinterpret_cast<uint4*>(skey)[tid * 2 + 1] =
                    make_uint4(key[4], key[5], key[6], key[7]);
                __syncthreads();
                const int ptid = tid ^ (j >> 3);
                uint4 o0 = reinterpret_cast<const uint4*>(skey)[ptid * 2];
                uint4 o1 = reinterpret_cast<const uint4*>(skey)[ptid * 2 + 1];
                unsigned oth[ELEMS] = {o0.x, o0.y, o0.z, o0.w,
                                       o1.x, o1.y, o1.z, o1.w};
                const bool lower = ((tid & (j >> 3)) == 0);
                #pragma unroll
                for (int e = 0; e < ELEMS; ++e) {
                    bool asc     = (((tid * ELEMS + e) & k) == 0);
                    bool keepmin = (lower == asc);
                    unsigned lo = min(key[e], oth[e]);
                    unsigned hi = max(key[e], oth[e]);
                    key[e] = keepmin ? lo : hi;
                }
            }
        }
    }

    // ---- boundary: first key of the next thread (for the e==7 window) ----
    __syncthreads();                 // last SMEM pass's readers are done
    skey[tid] = key[0];
    __syncthreads();
    float t_next = 0.0f;
    if (tid < THREADS - 1) t_next = st_orig[skey[tid + 1] & 1023u];

    // ---- gather exact (t, w) in sorted order ----
    float lt[ELEMS], lw[ELEMS];
    #pragma unroll
    for (int e = 0; e < ELEMS; ++e) {
        int idx = key[e] & 1023u;
        lt[e] = st_orig[idx];
        lw[e] = sw_orig[idx];
    }

    // ---- scan bases: per-thread totals -> warp scan -> 4-warp combine ----
    float cw = 0.0f, cwt = 0.0f;
    #pragma unroll
    for (int e = 0; e < ELEMS; ++e) {
        cw  += lw[e];
        cwt += lw[e] * lt[e];
    }
    float scw = cw, scwt = cwt;
    #pragma unroll
    for (int off = 1; off < 32; off <<= 1) {
        float a  = __shfl_up_sync(0xffffffffu, scw,  off);
        float a2 = __shfl_up_sync(0xffffffffu, scwt, off);
        if (lane >= off) { scw += a; scwt += a2; }
    }
    if (lane == 31) { s_ww[wid] = scw; s_wwt[wid] = scwt; }
    __syncthreads();
    float basew  = scw  - cw;    // exclusive within warp
    float basewt = scwt - cwt;
    if (wid > 0) { basew += s_ww[0]; basewt += s_wwt[0]; }
    if (wid > 1) { basew += s_ww[1]; basewt += s_wwt[1]; }
    if (wid > 2) { basew += s_ww[2]; basewt += s_wwt[2]; }

    // ---- candidate solve + causal window + local min (fused scan) ----
    const float theta = thresholds[post];
    const float INF   = f_inf();
    float rcw = basew, rcwt = basewt;
    float vmin = INF;
    #pragma unroll
    for (int e = 0; e < ELEMS; ++e) {
        rcw  += lw[e];
        rcwt += lw[e] * lt[e];
        float tmp = (rcw > 0.0f) ? __fdividef(theta + rcwt, rcw) : INF;
        bool  bad = (tmp < lt[e]);
        if (e < ELEMS - 1) {
            bad = bad || (tmp > lt[e + 1]);
        } else if (tid < THREADS - 1) {
            bad = bad || (tmp > t_next);
        }
        if (!bad) vmin = fminf(vmin, tmp);
    }

    // ---- block min-reduce ----
    #pragma unroll
    for (int off = 16; off > 0; off >>= 1)
        vmin = fminf(vmin, __shfl_down_sync(0xffffffffu, vmin, off));
    if (lane == 0) s_red[wid] = vmin;
    __syncthreads();
    if (tid == 0) {
        float m = fminf(fminf(s_red[0], s_red[1]), fminf(s_red[2], s_red[3]));
        out[b * POST + post] = m;
    }
}

// ---------------------------------------------------------------------------
extern "C" void kernel_launch(void* const* d_in, const int* in_sizes, int n_in,
                              void* d_out, int out_size) {
    const float* spikes     = (const float*)d_in[0];  // [B, PRE]
    const float* weights    = (const float*)d_in[1];  // [PRE, POST]
    const float* delays     = (const float*)d_in[2];  // [PRE, POST]
    const float* thresholds = (const float*)d_in[3];  // [POST]

    const int B = in_sizes[0] / PRE;

    dim3 t_tb(32, 8);
    dim3 t_tg(POST / 32, PRE / 32, 2);
    transpose2_kernel<<<t_tg, t_tb>>>(weights, delays);

    equaltime_kernel<<<B * POST, THREADS>>>(spikes, thresholds,
                                            (float*)d_out, B);
}

// round 17
// speedup vs baseline: 7.9669x; 1.2402x over previous
#include <cuda_runtime.h>
#include <cuda_bf16.h>

#define PRE     1024
#define POST    1024
#define THREADS 128
#define ELEMS   8       // full-path elements per thread (1024/128)
#define KELEMS  4       // kept-path elements per thread (512/128)
#define KCAP    512
#define TAU     0.85f

// Scratch for transposed weights/delays: [POST, PRE] row-major.
__device__ float g_wT[POST * PRE];
__device__ float g_dT[POST * PRE];

__device__ __forceinline__ float f_inf() { return __int_as_float(0x7f800000); }

// ---------------------------------------------------------------------------
__global__ void transpose2_kernel(const float* __restrict__ w,
                                  const float* __restrict__ d) {
    __shared__ float tile[32][33];
    const float* src = (blockIdx.z == 0) ? w : d;
    float* dst       = (blockIdx.z == 0) ? g_wT : g_dT;

    int col = blockIdx.x * 32 + threadIdx.x;
    int row = blockIdx.y * 32 + threadIdx.y;
    #pragma unroll
    for (int i = 0; i < 32; i += 8)
        tile[threadIdx.y + i][threadIdx.x] = src[(row + i) * POST + col];
    __syncthreads();
    int dcol = blockIdx.y * 32 + threadIdx.x;
    int drow = blockIdx.x * 32 + threadIdx.y;
    #pragma unroll
    for (int i = 0; i < 32; i += 8)
        dst[(drow + i) * PRE + dcol] = tile[threadIdx.x][threadIdx.y + i];
}

// ---------------------------------------------------------------------------
// Bitonic sort of L packed keys, blocked layout (thread owns positions
// tid*EL .. tid*EL+EL-1).  j < EL in-register; j < 32*EL via shuffle;
// larger j via SMEM round trips through skey.
// ---------------------------------------------------------------------------
template<int L, int EL>
__device__ __forceinline__ void bitonic_sort(unsigned (&key)[EL],
                                             unsigned* skey, int tid) {
    #pragma unroll
    for (int k = 2; k <= L; k <<= 1) {
        #pragma unroll
        for (int j = k >> 1; j > 0; j >>= 1) {
            if (j < EL) {
                #pragma unroll
                for (int e = 0; e < EL; ++e) {
                    if ((e & j) == 0) {
                        const int e2 = e | j;
                        const bool asc = (((tid * EL + e) & k) == 0);
                        unsigned a = key[e], b = key[e2];
                        unsigned lo = min(a, b), hi = max(a, b);
                        key[e]  = asc ? lo : hi;
                        key[e2] = asc ? hi : lo;
                    }
                }
            } else if (j < 32 * EL) {
                const int jw = j / EL;
                const bool lower = ((tid & jw) == 0);
                #pragma unroll
                for (int e = 0; e < EL; ++e) {
                    unsigned oth = __shfl_xor_sync(0xffffffffu, key[e], jw);
                    const bool asc = (((tid * EL + e) & k) == 0);
                    key[e] = ((lower == asc)) ? min(key[e], oth)
                                              : max(key[e], oth);
                }
            } else {
                __syncthreads();
                #pragma unroll
                for (int v = 0; v < EL / 4; ++v)
                    reinterpret_cast<uint4*>(skey)[tid * (EL / 4) + v] =
                        make_uint4(key[v*4], key[v*4+1], key[v*4+2], key[v*4+3]);
                __syncthreads();
                const int  ptid  = tid ^ (j / EL);
                const bool lower = ((tid & (j / EL)) == 0);
                #pragma unroll
                for (int v = 0; v < EL / 4; ++v) {
                    uint4 o = reinterpret_cast<const uint4*>(skey)[ptid * (EL / 4) + v];
                    unsigned ov[4] = {o.x, o.y, o.z, o.w};
                    #pragma unroll
                    for (int q = 0; q < 4; ++q) {
                        const int  e   = v * 4 + q;
                        const bool asc = (((tid * EL + e) & k) == 0);
                        key[e] = ((lower == asc)) ? min(key[e], ov[q])
                                                  : max(key[e], ov[q]);
                    }
                }
            }
        }
    }
}

// ---------------------------------------------------------------------------
// Scan + candidate solve + block min over a sorted key list.
// CLAMP=true (kept path): window upper bound is min(next_time, taup);
//   padded keys (0xFFFFFFFF) act as t=INF, w=0 and self-exclude.
// CLAMP=false (full path): last global element has no upper bound.
// Returns the block-wide min to ALL threads.
// ---------------------------------------------------------------------------
template<int EL, bool CLAMP>
__device__ __forceinline__ float solve_sorted(const unsigned (&key)[EL],
                                              const float* st_orig,
                                              const float* sw_orig,
                                              unsigned* skey,
                                              float theta, float taup,
                                              int tid, int lane, int wid,
                                              float* s_ww, float* s_wwt,
                                              float* s_red) {
    const float INF = f_inf();

    // boundary: next thread's first element time
    __syncthreads();
    skey[tid] = key[0];
    __syncthreads();
    float t_next = INF;
    if (tid < THREADS - 1) {
        unsigned nk = skey[tid + 1];
        bool npad = CLAMP && (nk == 0xFFFFFFFFu);
        float tv = st_orig[nk & 1023u];
        t_next = npad ? INF : tv;
    }

    // gather exact (t, w) in sorted order
    float lt[EL], lw[EL];
    #pragma unroll
    for (int e = 0; e < EL; ++e) {
        bool pad = CLAMP && (key[e] == 0xFFFFFFFFu);
        int  idx = key[e] & 1023u;
        float tv = st_orig[idx];
        float wv = sw_orig[idx];
        lt[e] = pad ? INF  : tv;
        lw[e] = pad ? 0.0f : wv;
    }

    // per-thread totals -> warp scan -> 4-warp combine (exclusive base)
    float cw = 0.0f, cwt = 0.0f;
    #pragma unroll
    for (int e = 0; e < EL; ++e) { cw += lw[e]; cwt += lw[e] * lt[e]; }
    // note: lw=0 on pads => lw*lt = 0*INF = NaN!  guard: use 0 explicitly.
    if (CLAMP) {
        cw = 0.0f; cwt = 0.0f;
        #pragma unroll
        for (int e = 0; e < EL; ++e) {
            float c = lw[e] * lt[e];
            cwt += (lw[e] == 0.0f) ? 0.0f : c;
            cw  += lw[e];
        }
    }
    float scw = cw, scwt = cwt;
    #pragma unroll
    for (int off = 1; off < 32; off <<= 1) {
        float a  = __shfl_up_sync(0xffffffffu, scw,  off);
        float a2 = __shfl_up_sync(0xffffffffu, scwt, off);
        if (lane >= off) { scw += a; scwt += a2; }
    }
    if (lane == 31) { s_ww[wid] = scw; s_wwt[wid] = scwt; }
    __syncthreads();
    float basew  = scw  - cw;
    float basewt = scwt - cwt;
    if (wid > 0) { basew += s_ww[0]; basewt += s_wwt[0]; }
    if (wid > 1) { basew += s_ww[1]; basewt += s_wwt[1]; }
    if (wid > 2) { basew += s_ww[2]; basewt += s_wwt[2]; }

    // candidates + causal window + local min
    float rcw = basew, rcwt = basewt;
    float vmin = INF;
    #pragma unroll
    for (int e = 0; e < EL; ++e) {
        float c = lw[e] * lt[e];
        rcw  += lw[e];
        rcwt += (CLAMP && lw[e] == 0.0f) ? 0.0f : c;
        float tmp = (rcw > 0.0f) ? __fdividef(theta + rcwt, rcw) : INF;
        bool  bad = (tmp < lt[e]);
        float nxt = (e < EL - 1) ? lt[e + 1] : t_next;
        if (CLAMP) {
            float ub = fminf(nxt, taup);
            bad = bad || (tmp > ub);
        } else {
            if (!(e == EL - 1 && tid == THREADS - 1))
                bad = bad || (tmp > nxt);
        }
        if (!bad) vmin = fminf(vmin, tmp);
    }

    // block min-reduce, broadcast to all threads
    #pragma unroll
    for (int off = 16; off > 0; off >>= 1)
        vmin = fminf(vmin, __shfl_down_sync(0xffffffffu, vmin, off));
    if (lane == 0) s_red[wid] = vmin;
    __syncthreads();
    return fminf(fminf(s_red[0], s_red[1]), fminf(s_red[2], s_red[3]));
}

// ---------------------------------------------------------------------------
__global__ __launch_bounds__(THREADS)
void equaltime_kernel(const float* __restrict__ spikes,
                      const float* __restrict__ thresholds,
                      float* __restrict__ out,
                      int B) {
    __shared__ float    st_orig[PRE];
    __shared__ float    sw_orig[PRE];
    __shared__ unsigned skey[PRE];
    __shared__ float    s_ww[4], s_wwt[4], s_red[4];
    __shared__ int      s_cnt;
    __shared__ int      s_taup_bits;

    const int tid  = threadIdx.x;
    const int lane = tid & 31;
    const int wid  = tid >> 5;

    const int b    = blockIdx.x % B;     // b fastest: 32 blocks share post rows
    const int post = blockIdx.x / B;
    const float INF = f_inf();

    const float* sp = spikes + b * PRE;
    const float* dT = g_dT + post * PRE;
    const float* wT = g_wT + post * PRE;

    // ---- load (blocked indices tid*8+e), stash originals ----
    float rt[ELEMS];
    #pragma unroll
    for (int v = 0; v < 2; ++v) {
        float4 s4 = reinterpret_cast<const float4*>(sp)[tid * 2 + v];
        float4 d4 = reinterpret_cast<const float4*>(dT)[tid * 2 + v];
        float4 w4 = reinterpret_cast<const float4*>(wT)[tid * 2 + v];
        float4 t4 = make_float4(s4.x + d4.x, s4.y + d4.y,
                                s4.z + d4.z, s4.w + d4.w);
        reinterpret_cast<float4*>(st_orig)[tid * 2 + v] = t4;
        reinterpret_cast<float4*>(sw_orig)[tid * 2 + v] = w4;
        rt[v * 4 + 0] = t4.x; rt[v * 4 + 1] = t4.y;
        rt[v * 4 + 2] = t4.z; rt[v * 4 + 3] = t4.w;
    }

    // ---- init pads + counters ----
    if (tid == 0) { s_cnt = 0; s_taup_bits = 0x7f800000; }
    #pragma unroll
    for (int v = 0; v < KCAP / THREADS; ++v)
        skey[tid + v * THREADS] = 0xFFFFFFFFu;
    __syncthreads();

    // ---- filter t < TAU, compact packed keys into skey[0..m) ----
    float texcl = INF;
    #pragma unroll
    for (int e = 0; e < ELEMS; ++e) {
        const int i = tid * ELEMS + e;
        float t    = rt[e];
        bool keep  = (t < TAU);
        unsigned mask = __ballot_sync(0xffffffffu, keep);
        int base = 0;
        if (lane == 0) base = atomicAdd(&s_cnt, __popc(mask));
        base = __shfl_sync(0xffffffffu, base, 0);
        if (keep) {
            int slot = base + __popc(mask & ((1u << lane) - 1u));
            skey[slot] = (__float_as_uint(t) & 0xFFFFFC00u) | (unsigned)i;
        } else {
            texcl = fminf(texcl, t);
        }
    }
    #pragma unroll
    for (int off = 16; off > 0; off >>= 1)
        texcl = fminf(texcl, __shfl_xor_sync(0xffffffffu, texcl, off));
    if (lane == 0) atomicMin(&s_taup_bits, __float_as_int(texcl));
    __syncthreads();

    const int   m    = s_cnt;
    const float taup = __int_as_float(s_taup_bits);
    const float theta = thresholds[post];

    // ---- kept path: 512-sort (covers the global min whenever a kept
    //      candidate exists: kept candidates < taup <= any excluded-prefix
    //      candidate) ----
    float result = INF;
    bool  need_full = (m > KCAP);
    if (!need_full) {
        unsigned key4[KELEMS];
        uint4 kk = reinterpret_cast<const uint4*>(skey)[tid];
        key4[0] = kk.x; key4[1] = kk.y; key4[2] = kk.z; key4[3] = kk.w;
        bitonic_sort<KCAP, KELEMS>(key4, skey, tid);
        result = solve_sorted<KELEMS, true>(key4, st_orig, sw_orig, skey,
                                            theta, taup, tid, lane, wid,
                                            s_ww, s_wwt, s_red);
        need_full = !(result < INF);
    }

    // ---- fallback: exact full 1024 sort (rare) ----
    if (need_full) {
        __syncthreads();
        unsigned key8[ELEMS];
        #pragma unroll
        for (int e = 0; e < ELEMS; ++e) {
            const int i = tid * ELEMS + e;
            key8[e] = (__float_as_uint(st_orig[i]) & 0xFFFFFC00u) | (unsigned)i;
        }
        bitonic_sort<PRE, ELEMS>(key8, skey, tid);
        result = solve_sorted<ELEMS, false>(key8, st_orig, sw_orig, skey,
                                            theta, INF, tid, lane, wid,
                                            s_ww, s_wwt, s_red);
    }

    if (tid == 0) out[b * POST + post] = result;
}

// ---------------------------------------------------------------------------
extern "C" void kernel_launch(void* const* d_in, const int* in_sizes, int n_in,
                              void* d_out, int out_size) {
    const float* spikes     = (const float*)d_in[0];  // [B, PRE]
    const float* weights    = (const float*)d_in[1];  // [PRE, POST]
    const float* delays     = (const float*)d_in[2];  // [PRE, POST]
    const float* thresholds = (const float*)d_in[3];  // [POST]

    const int B = in_sizes[0] / PRE;

    dim3 t_tb(32, 8);
    dim3 t_tg(POST / 32, PRE / 32, 2);
    transpose2_kernel<<<t_tg, t_tb>>>(weights, delays);

    equaltime_kernel<<<B * POST, THREADS>>>(spikes, thresholds,
                                            (float*)d_out, B);
}